// round 1
// baseline (speedup 1.0000x reference)
#include <cuda_runtime.h>
#include <math.h>

// Problem constants
#define T_TOK 4096      // B*S tokens
#define DIM   1024      // D
#define NEXP  8         // experts
#define HID   2816      // hidden
#define NSLOT (T_TOK*2) // total token-expert assignments (top-2)

// GEMM tiling
#define BM 64
#define BN 64
#define BK 16

// ---------------- scratch (static __device__, no allocs) ----------------
__device__ float g_H[(long long)NSLOT * HID];   // post-SwiGLU hidden, per slot (92.3 MB)
__device__ float g_Y[(long long)NSLOT * DIM];   // per-slot expert output   (33.5 MB)
__device__ int   g_tok[NSLOT];                  // slot -> token
__device__ int   g_slot[NSLOT];                 // token*2+k -> slot
__device__ int   g_te[NSLOT];                   // token*2+k -> expert
__device__ float g_tw[NSLOT];                   // token*2+k -> gate weight (raw logit)
__device__ int   g_cnt[NEXP];
__device__ int   g_off[NEXP + 1];
__device__ int   g_cur[NEXP];

// ---------------- K0: reset counters ----------------
__global__ void k_zero_cnt() {
    if (threadIdx.x < NEXP) g_cnt[threadIdx.x] = 0;
}

// ---------------- K1: gating scores + top-2 ----------------
// one warp per token; Wg is 32KB -> L1-resident
__global__ void k_gate(const float* __restrict__ x, const float* __restrict__ Wg) {
    int t = (blockIdx.x * blockDim.x + threadIdx.x) >> 5;
    int lane = threadIdx.x & 31;
    if (t >= T_TOK) return;
    const float4* xr = reinterpret_cast<const float4*>(x + (long long)t * DIM);
    float s[NEXP];
#pragma unroll
    for (int e = 0; e < NEXP; e++) s[e] = 0.f;
    for (int i = lane; i < DIM / 4; i += 32) {
        float4 xv = xr[i];
#pragma unroll
        for (int e = 0; e < NEXP; e++) {
            float4 wv = reinterpret_cast<const float4*>(Wg + (long long)e * DIM)[i];
            s[e] += xv.x * wv.x + xv.y * wv.y + xv.z * wv.z + xv.w * wv.w;
        }
    }
#pragma unroll
    for (int e = 0; e < NEXP; e++) {
#pragma unroll
        for (int o = 16; o > 0; o >>= 1) s[e] += __shfl_xor_sync(0xffffffffu, s[e], o);
    }
    if (lane == 0) {
        int b0 = 0; float v0 = s[0];
#pragma unroll
        for (int e = 1; e < NEXP; e++) if (s[e] > v0) { v0 = s[e]; b0 = e; }
        int b1 = -1; float v1 = -3.4e38f;
#pragma unroll
        for (int e = 0; e < NEXP; e++) if (e != b0 && s[e] > v1) { v1 = s[e]; b1 = e; }
        g_te[t * 2 + 0] = b0;  g_te[t * 2 + 1] = b1;
        g_tw[t * 2 + 0] = v0;  g_tw[t * 2 + 1] = v1;
        atomicAdd(&g_cnt[b0], 1);
        atomicAdd(&g_cnt[b1], 1);
    }
}

// ---------------- K2: exclusive scan of 8 counts ----------------
__global__ void k_scan() {
    int o = 0;
    for (int e = 0; e < NEXP; e++) { g_off[e] = o; g_cur[e] = o; o += g_cnt[e]; }
    g_off[NEXP] = o;
}

// ---------------- K3: assign slots ----------------
__global__ void k_assign() {
    int t = blockIdx.x * blockDim.x + threadIdx.x;
    if (t >= T_TOK) return;
#pragma unroll
    for (int k = 0; k < 2; k++) {
        int e = g_te[t * 2 + k];
        int pos = atomicAdd(&g_cur[e], 1);
        g_tok[pos] = t;
        g_slot[t * 2 + k] = pos;
    }
}

// ---------------- K4: fused grouped GEMM1: H = silu(X@W1^T) * (X@W2^T) ----------------
// grid: (HID/BN, maxRowTiles, NEXP); A rows gathered via g_tok
__global__ void __launch_bounds__(256) k_ffn1(const float* __restrict__ x,
                                              const float* __restrict__ W1,
                                              const float* __restrict__ W2) {
    int e = blockIdx.z;
    int rbeg = g_off[e], rend = g_off[e + 1];
    int row0 = rbeg + blockIdx.y * BM;
    if (row0 >= rend) return;
    int n0 = blockIdx.x * BN;

    __shared__ float As[BK][BM];
    __shared__ float B1s[BK][BN];
    __shared__ float B2s[BK][BN];

    int tid = threadIdx.x;
    int ty = tid >> 4, tx = tid & 15;
    int lr = tid >> 2;            // 0..63 row within tile
    int lk = (tid & 3) << 2;      // 0,4,8,12 k-offset (float4)

    int arow = row0 + lr;
    const float* aptr = (arow < rend) ? x + (long long)g_tok[arow] * DIM : nullptr;
    const float* b1p = W1 + (long long)e * HID * DIM + (long long)(n0 + lr) * DIM;
    const float* b2p = W2 + (long long)e * HID * DIM + (long long)(n0 + lr) * DIM;

    float acc1[4][4] = {}, acc2[4][4] = {};

    for (int k0 = 0; k0 < DIM; k0 += BK) {
        float4 av = aptr ? *reinterpret_cast<const float4*>(aptr + k0 + lk)
                         : make_float4(0.f, 0.f, 0.f, 0.f);
        float4 b1 = *reinterpret_cast<const float4*>(b1p + k0 + lk);
        float4 b2 = *reinterpret_cast<const float4*>(b2p + k0 + lk);
        As[lk + 0][lr] = av.x; As[lk + 1][lr] = av.y; As[lk + 2][lr] = av.z; As[lk + 3][lr] = av.w;
        B1s[lk + 0][lr] = b1.x; B1s[lk + 1][lr] = b1.y; B1s[lk + 2][lr] = b1.z; B1s[lk + 3][lr] = b1.w;
        B2s[lk + 0][lr] = b2.x; B2s[lk + 1][lr] = b2.y; B2s[lk + 2][lr] = b2.z; B2s[lk + 3][lr] = b2.w;
        __syncthreads();
#pragma unroll
        for (int k = 0; k < BK; k++) {
            float4 a = *reinterpret_cast<const float4*>(&As[k][ty * 4]);
            float4 u = *reinterpret_cast<const float4*>(&B1s[k][tx * 4]);
            float4 v = *reinterpret_cast<const float4*>(&B2s[k][tx * 4]);
            float aa[4] = {a.x, a.y, a.z, a.w};
            float uu[4] = {u.x, u.y, u.z, u.w};
            float vv[4] = {v.x, v.y, v.z, v.w};
#pragma unroll
            for (int i = 0; i < 4; i++)
#pragma unroll
                for (int j = 0; j < 4; j++) {
                    acc1[i][j] += aa[i] * uu[j];
                    acc2[i][j] += aa[i] * vv[j];
                }
        }
        __syncthreads();
    }

#pragma unroll
    for (int i = 0; i < 4; i++) {
        int r = row0 + ty * 4 + i;
        if (r >= rend) continue;
        float* hp = g_H + (long long)r * HID + n0 + tx * 4;
#pragma unroll
        for (int j = 0; j < 4; j++) {
            float g = acc1[i][j];
            float sg = g / (1.f + expf(-g));   // silu, accurate expf
            hp[j] = sg * acc2[i][j];
        }
    }
}

// ---------------- K5: grouped GEMM2: Y = H @ W3^T ----------------
// W3[e] is [D, H] row-major -> B[n=d][k=h] contiguous along k. K = HID.
__global__ void __launch_bounds__(256) k_ffn2(const float* __restrict__ W3) {
    int e = blockIdx.z;
    int rbeg = g_off[e], rend = g_off[e + 1];
    int row0 = rbeg + blockIdx.y * BM;
    if (row0 >= rend) return;
    int n0 = blockIdx.x * BN;

    __shared__ float As[BK][BM];
    __shared__ float Bs[BK][BN];

    int tid = threadIdx.x;
    int ty = tid >> 4, tx = tid & 15;
    int lr = tid >> 2;
    int lk = (tid & 3) << 2;

    int arow = row0 + lr;
    const float* aptr = (arow < rend) ? g_H + (long long)arow * HID : nullptr;
    const float* bp = W3 + (long long)e * DIM * HID + (long long)(n0 + lr) * HID;

    float acc[4][4] = {};

    for (int k0 = 0; k0 < HID; k0 += BK) {
        float4 av = aptr ? *reinterpret_cast<const float4*>(aptr + k0 + lk)
                         : make_float4(0.f, 0.f, 0.f, 0.f);
        float4 bv = *reinterpret_cast<const float4*>(bp + k0 + lk);
        As[lk + 0][lr] = av.x; As[lk + 1][lr] = av.y; As[lk + 2][lr] = av.z; As[lk + 3][lr] = av.w;
        Bs[lk + 0][lr] = bv.x; Bs[lk + 1][lr] = bv.y; Bs[lk + 2][lr] = bv.z; Bs[lk + 3][lr] = bv.w;
        __syncthreads();
#pragma unroll
        for (int k = 0; k < BK; k++) {
            float4 a = *reinterpret_cast<const float4*>(&As[k][ty * 4]);
            float4 b = *reinterpret_cast<const float4*>(&Bs[k][tx * 4]);
            float aa[4] = {a.x, a.y, a.z, a.w};
            float bb[4] = {b.x, b.y, b.z, b.w};
#pragma unroll
            for (int i = 0; i < 4; i++)
#pragma unroll
                for (int j = 0; j < 4; j++)
                    acc[i][j] += aa[i] * bb[j];
        }
        __syncthreads();
    }

#pragma unroll
    for (int i = 0; i < 4; i++) {
        int r = row0 + ty * 4 + i;
        if (r >= rend) continue;
        float* yp = g_Y + (long long)r * DIM + n0 + tx * 4;
#pragma unroll
        for (int j = 0; j < 4; j++) yp[j] = acc[i][j];
    }
}

// ---------------- K6: combine: out[t] = w0*Y[s0] + w1*Y[s1] ----------------
__global__ void k_combine(float* __restrict__ out) {
    int t = blockIdx.x;
    int s0 = g_slot[t * 2 + 0], s1 = g_slot[t * 2 + 1];
    float w0 = g_tw[t * 2 + 0], w1 = g_tw[t * 2 + 1];
    const float4* y0 = reinterpret_cast<const float4*>(g_Y + (long long)s0 * DIM);
    const float4* y1 = reinterpret_cast<const float4*>(g_Y + (long long)s1 * DIM);
    float4* op = reinterpret_cast<float4*>(out + (long long)t * DIM);
    for (int i = threadIdx.x; i < DIM / 4; i += blockDim.x) {
        float4 a = y0[i], b = y1[i], o;
        o.x = w0 * a.x + w1 * b.x;
        o.y = w0 * a.y + w1 * b.y;
        o.z = w0 * a.z + w1 * b.z;
        o.w = w0 * a.w + w1 * b.w;
        op[i] = o;
    }
}

// ---------------- launch ----------------
extern "C" void kernel_launch(void* const* d_in, const int* in_sizes, int n_in,
                              void* d_out, int out_size) {
    const float* x  = (const float*)d_in[0];
    const float* Wg = (const float*)d_in[1];
    const float* W1 = (const float*)d_in[2];
    const float* W2 = (const float*)d_in[3];
    const float* W3 = (const float*)d_in[4];
    float* out = (float*)d_out;

    k_zero_cnt<<<1, 32>>>();
    k_gate<<<T_TOK / 8, 256>>>(x, Wg);        // 8 warps/block, 1 warp/token
    k_scan<<<1, 1>>>();
    k_assign<<<T_TOK / 256, 256>>>();
    // worst case: all tokens pick the same expert -> T_TOK rows -> 64 row-tiles
    k_ffn1<<<dim3(HID / BN, T_TOK / BM, NEXP), 256>>>(x, W1, W2);
    k_ffn2<<<dim3(DIM / BN, T_TOK / BM, NEXP), 256>>>(W3);
    k_combine<<<T_TOK, 256>>>(out);
}

// round 3
// speedup vs baseline: 2.6216x; 2.6216x over previous
#include <cuda_runtime.h>
#include <cuda_bf16.h>
#include <math.h>
#include <stdint.h>

#define T_TOK 4096
#define DIM   1024
#define NEXP  8
#define HID   2816
#define NSLOT (T_TOK*2)

typedef unsigned long long ull;

// ---------------- device scratch (no allocs) ----------------
__device__ uint32_t g_Hpk[(size_t)NSLOT * HID];  // packed (hi,lo) bf16 of H
__device__ int   g_tok[NSLOT];
__device__ float g_wslot[NSLOT];
__device__ int   g_te[NSLOT];
__device__ float g_tw[NSLOT];
__device__ int   g_cnt[NEXP];
__device__ int   g_off[NEXP + 1];
__device__ int   g_cur[NEXP];

// ---------------- helpers ----------------
__device__ __forceinline__ uint32_t s2u(const void* p) {
    uint32_t a;
    asm("{ .reg .u64 t; cvta.to.shared.u64 t, %1; cvt.u32.u64 %0, t; }" : "=r"(a) : "l"(p));
    return a;
}
// pack halves: low = first elem, high = second elem
__device__ __forceinline__ unsigned bfpack(float lo_elem, float hi_elem) {
    unsigned r;
    asm("cvt.rn.bf16x2.f32 %0, %1, %2;" : "=r"(r) : "f"(hi_elem), "f"(lo_elem));
    return r;
}
// split 4 fp32 into hi/lo bf16 quads (element order preserved)
__device__ __forceinline__ void split4(float4 v, ull& h, ull& l) {
    unsigned h0 = bfpack(v.x, v.y);
    unsigned h1 = bfpack(v.z, v.w);
    float f0 = __uint_as_float(h0 << 16);
    float f1 = __uint_as_float(h0 & 0xffff0000u);
    float f2 = __uint_as_float(h1 << 16);
    float f3 = __uint_as_float(h1 & 0xffff0000u);
    unsigned l0 = bfpack(v.x - f0, v.y - f1);
    unsigned l1 = bfpack(v.z - f2, v.w - f3);
    h = (ull)h0 | ((ull)h1 << 32);
    l = (ull)l0 | ((ull)l1 << 32);
}
__device__ __forceinline__ uint32_t packhl(float v) {
    __nv_bfloat16 hb = __float2bfloat16(v);
    float hf = __bfloat162float(hb);
    __nv_bfloat16 lb = __float2bfloat16(v - hf);
    return (uint32_t)__bfloat16_as_ushort(hb) | ((uint32_t)__bfloat16_as_ushort(lb) << 16);
}
__device__ __forceinline__ void ldm4(uint32_t& r0, uint32_t& r1, uint32_t& r2, uint32_t& r3, uint32_t a) {
    asm volatile("ldmatrix.sync.aligned.m8n8.x4.shared.b16 {%0,%1,%2,%3}, [%4];"
        : "=r"(r0), "=r"(r1), "=r"(r2), "=r"(r3) : "r"(a));
}
__device__ __forceinline__ void mma16816(float* c, const uint32_t* a, const uint32_t* b) {
    asm volatile("mma.sync.aligned.m16n8k16.row.col.f32.bf16.bf16.f32 "
        "{%0,%1,%2,%3}, {%4,%5,%6,%7}, {%8,%9}, {%0,%1,%2,%3};"
        : "+f"(c[0]), "+f"(c[1]), "+f"(c[2]), "+f"(c[3])
        : "r"(a[0]), "r"(a[1]), "r"(a[2]), "r"(a[3]), "r"(b[0]), "r"(b[1]));
}

// smem geometry: rows padded to 40 halves (k32 + 8 pad) for conflict-free ldmatrix
#define ROWP  40
#define SSTR1 20480   // halves per stage, GEMM1: A(2x5120) + B1(2x2560) + B2(2x2560)
#define SSTR2 15360   // halves per stage, GEMM2: A(2x5120) + B(2x2560)
#define SMEM1 (2*SSTR1*2)
#define SMEM2 (2*SSTR2*2)

// ---------------- small kernels ----------------
__global__ void k_zero_cnt() { if (threadIdx.x < NEXP) g_cnt[threadIdx.x] = 0; }

__global__ void k_zero_out(float4* o) {
    o[blockIdx.x * 256 + threadIdx.x] = make_float4(0.f, 0.f, 0.f, 0.f);
}

__global__ void k_gate(const float* __restrict__ x, const float* __restrict__ Wg) {
    int t = (blockIdx.x * blockDim.x + threadIdx.x) >> 5;
    int lane = threadIdx.x & 31;
    if (t >= T_TOK) return;
    const float4* xr = reinterpret_cast<const float4*>(x + (size_t)t * DIM);
    float s[NEXP];
#pragma unroll
    for (int e = 0; e < NEXP; e++) s[e] = 0.f;
    for (int i = lane; i < DIM / 4; i += 32) {
        float4 xv = xr[i];
#pragma unroll
        for (int e = 0; e < NEXP; e++) {
            float4 wv = reinterpret_cast<const float4*>(Wg + (size_t)e * DIM)[i];
            s[e] += xv.x * wv.x + xv.y * wv.y + xv.z * wv.z + xv.w * wv.w;
        }
    }
#pragma unroll
    for (int e = 0; e < NEXP; e++) {
#pragma unroll
        for (int o = 16; o > 0; o >>= 1) s[e] += __shfl_xor_sync(0xffffffffu, s[e], o);
    }
    if (lane == 0) {
        int b0 = 0; float v0 = s[0];
#pragma unroll
        for (int e = 1; e < NEXP; e++) if (s[e] > v0) { v0 = s[e]; b0 = e; }
        int b1 = -1; float v1 = -3.4e38f;
#pragma unroll
        for (int e = 0; e < NEXP; e++) if (e != b0 && s[e] > v1) { v1 = s[e]; b1 = e; }
        g_te[t * 2 + 0] = b0;  g_te[t * 2 + 1] = b1;
        g_tw[t * 2 + 0] = v0;  g_tw[t * 2 + 1] = v1;
        atomicAdd(&g_cnt[b0], 1);
        atomicAdd(&g_cnt[b1], 1);
    }
}

__global__ void k_scan() {
    int o = 0;
    for (int e = 0; e < NEXP; e++) { g_off[e] = o; g_cur[e] = o; o += g_cnt[e]; }
    g_off[NEXP] = o;
}

__global__ void k_assign() {
    int t = blockIdx.x * blockDim.x + threadIdx.x;
    if (t >= T_TOK) return;
#pragma unroll
    for (int k = 0; k < 2; k++) {
        int e = g_te[t * 2 + k];
        int pos = atomicAdd(&g_cur[e], 1);
        g_tok[pos] = t;
        g_wslot[pos] = g_tw[t * 2 + k];
    }
}

// ---------------- GEMM1 compute step (one k32 chunk from smem) ----------------
__device__ __forceinline__ void comp1(uint32_t smb, int sb, int wid, int lane,
                                      float (&A1)[2][4][4], float (&A2)[2][4][4]) {
#pragma unroll
    for (int ks = 0; ks < 2; ks++) {
        uint32_t ah[2][4], al[2][4];
#pragma unroll
        for (int mt = 0; mt < 2; mt++) {
            int row = (wid & 3) * 32 + mt * 16 + (lane & 15);
            int hc = ks * 16 + ((lane & 16) >> 1);
            uint32_t ad = smb + (uint32_t)(sb + row * ROWP + hc) * 2;
            ldm4(ah[mt][0], ah[mt][1], ah[mt][2], ah[mt][3], ad);
            ldm4(al[mt][0], al[mt][1], al[mt][2], al[mt][3], ad + 5120 * 2);
        }
        uint32_t b1h[4][2], b1l[4][2], b2h[4][2], b2l[4][2];
#pragma unroll
        for (int p = 0; p < 2; p++) {
            int nr = (wid >> 2) * 32 + p * 16 + (lane & 7) + ((lane & 16) >> 1);
            int hc = ks * 16 + (lane & 8);
            uint32_t bd = smb + (uint32_t)(sb + 10240 + nr * ROWP + hc) * 2;
            ldm4(b1h[2*p][0], b1h[2*p][1], b1h[2*p+1][0], b1h[2*p+1][1], bd);
            ldm4(b1l[2*p][0], b1l[2*p][1], b1l[2*p+1][0], b1l[2*p+1][1], bd + 2560 * 2);
            ldm4(b2h[2*p][0], b2h[2*p][1], b2h[2*p+1][0], b2h[2*p+1][1], bd + 5120 * 2);
            ldm4(b2l[2*p][0], b2l[2*p][1], b2l[2*p+1][0], b2l[2*p+1][1], bd + 7680 * 2);
        }
#pragma unroll
        for (int mt = 0; mt < 2; mt++)
#pragma unroll
            for (int nt = 0; nt < 4; nt++) {
                mma16816(A1[mt][nt], ah[mt], b1h[nt]);
                mma16816(A1[mt][nt], ah[mt], b1l[nt]);
                mma16816(A1[mt][nt], al[mt], b1h[nt]);
                mma16816(A2[mt][nt], ah[mt], b2h[nt]);
                mma16816(A2[mt][nt], ah[mt], b2l[nt]);
                mma16816(A2[mt][nt], al[mt], b2h[nt]);
            }
    }
}

__device__ __forceinline__ void load1(const float* __restrict__ x, const int* s_tok,
        const float* __restrict__ W1p, const float* __restrict__ W2p,
        int k0, int tid, float4 (&rg)[8]) {
#pragma unroll
    for (int i = 0; i < 4; i++) {
        int idx = tid + (i << 8); int r = idx >> 3, cc = idx & 7;
        rg[i] = *(const float4*)(x + (size_t)s_tok[r] * DIM + k0 + cc * 4);
    }
#pragma unroll
    for (int i = 0; i < 2; i++) {
        int w = tid + (i << 8); int r = w >> 3, cc = w & 7;
        rg[4 + i] = *(const float4*)(W1p + (size_t)r * DIM + k0 + cc * 4);
    }
#pragma unroll
    for (int i = 0; i < 2; i++) {
        int w = tid + (i << 8); int r = w >> 3, cc = w & 7;
        rg[6 + i] = *(const float4*)(W2p + (size_t)r * DIM + k0 + cc * 4);
    }
}

__device__ __forceinline__ void sts1(uint16_t* sm16, int sb, int tid, const float4 (&rg)[8]) {
#pragma unroll
    for (int i = 0; i < 4; i++) {
        int idx = tid + (i << 8); int r = idx >> 3, cc = idx & 7;
        ull h, l; split4(rg[i], h, l);
        *(ull*)(sm16 + sb + r * ROWP + cc * 4) = h;
        *(ull*)(sm16 + sb + 5120 + r * ROWP + cc * 4) = l;
    }
#pragma unroll
    for (int i = 0; i < 2; i++) {
        int w = tid + (i << 8); int r = w >> 3, cc = w & 7;
        ull h, l; split4(rg[4 + i], h, l);
        *(ull*)(sm16 + sb + 10240 + r * ROWP + cc * 4) = h;
        *(ull*)(sm16 + sb + 12800 + r * ROWP + cc * 4) = l;
    }
#pragma unroll
    for (int i = 0; i < 2; i++) {
        int w = tid + (i << 8); int r = w >> 3, cc = w & 7;
        ull h, l; split4(rg[6 + i], h, l);
        *(ull*)(sm16 + sb + 15360 + r * ROWP + cc * 4) = h;
        *(ull*)(sm16 + sb + 17920 + r * ROWP + cc * 4) = l;
    }
}

// ---------------- GEMM1: H = silu(X@W1^T)*(X@W2^T), split-bf16 mma.sync ----------------
__global__ void __launch_bounds__(256, 1) k_ffn1(const float* __restrict__ x,
                                                 const float* __restrict__ W1,
                                                 const float* __restrict__ W2) {
    int e = blockIdx.z;
    int rbeg = g_off[e], rend = g_off[e + 1];
    int row0 = rbeg + blockIdx.y * 128;
    if (row0 >= rend) return;
    int n0 = blockIdx.x * 64;

    extern __shared__ __align__(16) uint16_t sm16[];
    __shared__ int s_tok[128];
    int tid = threadIdx.x, wid = tid >> 5, lane = tid & 31;
    uint32_t smb = s2u(sm16);

    if (tid < 128) {
        int rr = row0 + tid;
        s_tok[tid] = g_tok[rr < rend ? rr : rbeg];
    }
    __syncthreads();

    const float* W1p = W1 + ((size_t)e * HID + n0) * DIM;
    const float* W2p = W2 + ((size_t)e * HID + n0) * DIM;

    float acc1[2][4][4], acc2[2][4][4];
#pragma unroll
    for (int a = 0; a < 2; a++)
#pragma unroll
        for (int b = 0; b < 4; b++)
#pragma unroll
            for (int c = 0; c < 4; c++) { acc1[a][b][c] = 0.f; acc2[a][b][c] = 0.f; }

    float4 rg[8];
    const int NC = DIM / 32;  // 32
    load1(x, s_tok, W1p, W2p, 0, tid, rg);
    sts1(sm16, 0, tid, rg);
    load1(x, s_tok, W1p, W2p, 32, tid, rg);
    __syncthreads();

    for (int c = 0; c < NC; c++) {
        int sbA = (c & 1) * SSTR1;
        int sbB = ((c + 1) & 1) * SSTR1;
        if (c + 1 < NC) sts1(sm16, sbB, tid, rg);
        if (c + 2 < NC) load1(x, s_tok, W1p, W2p, (c + 2) * 32, tid, rg);
        comp1(smb, sbA, wid, lane, acc1, acc2);
        __syncthreads();
    }

    // epilogue: silu(g)*u, pack hi/lo, store
    int wm = wid & 3, wn = wid >> 2;
#pragma unroll
    for (int mt = 0; mt < 2; mt++) {
        int rbse = row0 + wm * 32 + mt * 16 + (lane >> 2);
#pragma unroll
        for (int h2 = 0; h2 < 2; h2++) {
            int row = rbse + h2 * 8;
            if (row >= rend) continue;
            uint32_t* hp = g_Hpk + (size_t)row * HID + n0 + wn * 32 + (lane & 3) * 2;
#pragma unroll
            for (int nt = 0; nt < 4; nt++) {
                float g0 = acc1[mt][nt][h2 * 2 + 0], u0 = acc2[mt][nt][h2 * 2 + 0];
                float g1 = acc1[mt][nt][h2 * 2 + 1], u1 = acc2[mt][nt][h2 * 2 + 1];
                float hv0 = g0 * u0 / (1.f + expf(-g0));
                float hv1 = g1 * u1 / (1.f + expf(-g1));
                uint2 pk; pk.x = packhl(hv0); pk.y = packhl(hv1);
                *(uint2*)(hp + nt * 8) = pk;
            }
        }
    }
}

// ---------------- GEMM2 pieces ----------------
__device__ __forceinline__ void comp2(uint32_t smb, int sb, int wid, int lane,
                                      float (&A)[2][4][4]) {
#pragma unroll
    for (int ks = 0; ks < 2; ks++) {
        uint32_t ah[2][4], al[2][4];
#pragma unroll
        for (int mt = 0; mt < 2; mt++) {
            int row = (wid & 3) * 32 + mt * 16 + (lane & 15);
            int hc = ks * 16 + ((lane & 16) >> 1);
            uint32_t ad = smb + (uint32_t)(sb + row * ROWP + hc) * 2;
            ldm4(ah[mt][0], ah[mt][1], ah[mt][2], ah[mt][3], ad);
            ldm4(al[mt][0], al[mt][1], al[mt][2], al[mt][3], ad + 5120 * 2);
        }
        uint32_t bh[4][2], bl[4][2];
#pragma unroll
        for (int p = 0; p < 2; p++) {
            int nr = (wid >> 2) * 32 + p * 16 + (lane & 7) + ((lane & 16) >> 1);
            int hc = ks * 16 + (lane & 8);
            uint32_t bd = smb + (uint32_t)(sb + 10240 + nr * ROWP + hc) * 2;
            ldm4(bh[2*p][0], bh[2*p][1], bh[2*p+1][0], bh[2*p+1][1], bd);
            ldm4(bl[2*p][0], bl[2*p][1], bl[2*p+1][0], bl[2*p+1][1], bd + 2560 * 2);
        }
#pragma unroll
        for (int mt = 0; mt < 2; mt++)
#pragma unroll
            for (int nt = 0; nt < 4; nt++) {
                mma16816(A[mt][nt], ah[mt], bh[nt]);
                mma16816(A[mt][nt], ah[mt], bl[nt]);
                mma16816(A[mt][nt], al[mt], bh[nt]);
            }
    }
}

__device__ __forceinline__ void load2(const int* s_row, const float* __restrict__ W3p,
                                      int k0, int tid, uint4 (&ua)[4], float4 (&ub)[2]) {
#pragma unroll
    for (int i = 0; i < 4; i++) {
        int idx = tid + (i << 8); int r = idx >> 3, cc = idx & 7;
        ua[i] = *(const uint4*)(g_Hpk + (size_t)s_row[r] * HID + k0 + cc * 4);
    }
#pragma unroll
    for (int i = 0; i < 2; i++) {
        int w = tid + (i << 8); int r = w >> 3, cc = w & 7;
        ub[i] = *(const float4*)(W3p + (size_t)r * HID + k0 + cc * 4);
    }
}

__device__ __forceinline__ void sts2(uint16_t* sm16, int sb, int tid,
                                     const uint4 (&ua)[4], const float4 (&ub)[2]) {
#pragma unroll
    for (int i = 0; i < 4; i++) {
        int idx = tid + (i << 8); int r = idx >> 3, cc = idx & 7;
        unsigned h01 = __byte_perm(ua[i].x, ua[i].y, 0x5410);
        unsigned h23 = __byte_perm(ua[i].z, ua[i].w, 0x5410);
        unsigned l01 = __byte_perm(ua[i].x, ua[i].y, 0x7632);
        unsigned l23 = __byte_perm(ua[i].z, ua[i].w, 0x7632);
        *(ull*)(sm16 + sb + r * ROWP + cc * 4) = (ull)h01 | ((ull)h23 << 32);
        *(ull*)(sm16 + sb + 5120 + r * ROWP + cc * 4) = (ull)l01 | ((ull)l23 << 32);
    }
#pragma unroll
    for (int i = 0; i < 2; i++) {
        int w = tid + (i << 8); int r = w >> 3, cc = w & 7;
        ull h, l; split4(ub[i], h, l);
        *(ull*)(sm16 + sb + 10240 + r * ROWP + cc * 4) = h;
        *(ull*)(sm16 + sb + 12800 + r * ROWP + cc * 4) = l;
    }
}

// ---------------- GEMM2: out[tok] += w * (H @ W3^T) ----------------
__global__ void __launch_bounds__(256, 2) k_ffn2(const float* __restrict__ W3,
                                                 float* __restrict__ out) {
    int e = blockIdx.z;
    int rbeg = g_off[e], rend = g_off[e + 1];
    int row0 = rbeg + blockIdx.y * 128;
    if (row0 >= rend) return;
    int n0 = blockIdx.x * 64;

    extern __shared__ __align__(16) uint16_t sm16[];
    __shared__ int s_row[128];
    int tid = threadIdx.x, wid = tid >> 5, lane = tid & 31;
    uint32_t smb = s2u(sm16);

    if (tid < 128) {
        int rr = row0 + tid;
        s_row[tid] = (rr < rend) ? rr : rbeg;
    }
    __syncthreads();

    const float* W3p = W3 + ((size_t)e * DIM + n0) * HID;

    float acc[2][4][4];
#pragma unroll
    for (int a = 0; a < 2; a++)
#pragma unroll
        for (int b = 0; b < 4; b++)
#pragma unroll
            for (int c = 0; c < 4; c++) acc[a][b][c] = 0.f;

    uint4 ua[4]; float4 ub[2];
    const int NC = HID / 32;  // 88
    load2(s_row, W3p, 0, tid, ua, ub);
    sts2(sm16, 0, tid, ua, ub);
    load2(s_row, W3p, 32, tid, ua, ub);
    __syncthreads();

    for (int c = 0; c < NC; c++) {
        int sbA = (c & 1) * SSTR2;
        int sbB = ((c + 1) & 1) * SSTR2;
        if (c + 1 < NC) sts2(sm16, sbB, tid, ua, ub);
        if (c + 2 < NC) load2(s_row, W3p, (c + 2) * 32, tid, ua, ub);
        comp2(smb, sbA, wid, lane, acc);
        __syncthreads();
    }

    // epilogue: scale by gate weight, atomicAdd into out
    int wm = wid & 3, wn = wid >> 2;
#pragma unroll
    for (int mt = 0; mt < 2; mt++) {
        int rbse = row0 + wm * 32 + mt * 16 + (lane >> 2);
#pragma unroll
        for (int h2 = 0; h2 < 2; h2++) {
            int slot = rbse + h2 * 8;
            if (slot >= rend) continue;
            int tk = g_tok[slot];
            float wv = g_wslot[slot];
            float* ob = out + (size_t)tk * DIM + n0 + wn * 32 + (lane & 3) * 2;
#pragma unroll
            for (int nt = 0; nt < 4; nt++) {
                atomicAdd(ob + nt * 8,     acc[mt][nt][h2 * 2 + 0] * wv);
                atomicAdd(ob + nt * 8 + 1, acc[mt][nt][h2 * 2 + 1] * wv);
            }
        }
    }
}

// ---------------- launch ----------------
extern "C" void kernel_launch(void* const* d_in, const int* in_sizes, int n_in,
                              void* d_out, int out_size) {
    const float* x  = (const float*)d_in[0];
    const float* Wg = (const float*)d_in[1];
    const float* W1 = (const float*)d_in[2];
    const float* W2 = (const float*)d_in[3];
    const float* W3 = (const float*)d_in[4];
    float* out = (float*)d_out;

    cudaFuncSetAttribute(k_ffn1, cudaFuncAttributeMaxDynamicSharedMemorySize, SMEM1);
    cudaFuncSetAttribute(k_ffn2, cudaFuncAttributeMaxDynamicSharedMemorySize, SMEM2);

    k_zero_cnt<<<1, 32>>>();
    k_zero_out<<<(T_TOK * DIM / 4) / 256, 256>>>((float4*)out);
    k_gate<<<T_TOK / 8, 256>>>(x, Wg);
    k_scan<<<1, 1>>>();
    k_assign<<<T_TOK / 256, 256>>>();
    k_ffn1<<<dim3(HID / 64, 32, NEXP), 256, SMEM1>>>(x, W1, W2);
    k_ffn2<<<dim3(DIM / 64, 32, NEXP), 256, SMEM2>>>(W3, out);
}